// round 1
// baseline (speedup 1.0000x reference)
#include <cuda_runtime.h>
#include <math.h>

#define B_DIM   4
#define S_DIM   8192
#define H_DIM   4096
#define RATIO   32
#define N_CHUNKS (S_DIM / RATIO)     /* 256 */
#define M_TOT   (B_DIM * S_DIM)      /* 32768 */
#define N_TOT   512                  /* 256 kv cols + 256 gate cols */

// Scratch: combined [kv | gate] intermediate, 32768 x 512 fp32 = 64 MB
__device__ __align__(16) float g_mid[(size_t)M_TOT * N_TOT];

// ---------------------------------------------------------------------------
// Kernel 1: C[M=32768, N=512] = hidden[M, 4096] @ [w_kv | w_gate]
// Classic 128x128x8 SGEMM tile, 256 threads, 8x8 microtile,
// smem double buffering + register prefetch of next global tile.
// ---------------------------------------------------------------------------
__global__ __launch_bounds__(256, 2)
void gemm_kernel(const float* __restrict__ A,
                 const float* __restrict__ Wkv,
                 const float* __restrict__ Wg)
{
    const int bx = blockIdx.x;   // 0..3 : which 128-col slab of the 512 output cols
    const int by = blockIdx.y;   // 0..255 : which 128-row slab
    const float* W = (bx < 2) ? Wkv : Wg;
    const int wcol0 = (bx & 1) * 128;   // column offset inside the 256-wide weight

    __shared__ __align__(16) float As[2][8][128];
    __shared__ __align__(16) float Bs[2][8][128];

    const int tid   = threadIdx.x;
    const int a_row = tid >> 1;          // 0..127
    const int a_col = (tid & 1) << 2;    // 0 or 4
    const int b_row = tid >> 5;          // 0..7
    const int b_col = (tid & 31) << 2;   // 0..124

    const float* Aptr = A + (size_t)(by * 128 + a_row) * H_DIM + a_col;
    const float* Wptr = W + b_row * 256 + wcol0 + b_col;

    const int ty = tid >> 4;   // 0..15 -> output rows ty*8..ty*8+7
    const int tx = tid & 15;   // 0..15 -> output cols tx*8..tx*8+7

    float acc[8][8];
#pragma unroll
    for (int i = 0; i < 8; i++)
#pragma unroll
        for (int j = 0; j < 8; j++) acc[i][j] = 0.f;

    // preload tile 0
    float4 a4 = *(const float4*)(Aptr);
    float4 b4 = *(const float4*)(Wptr);

    int buf = 0;
    As[buf][a_col + 0][a_row] = a4.x;
    As[buf][a_col + 1][a_row] = a4.y;
    As[buf][a_col + 2][a_row] = a4.z;
    As[buf][a_col + 3][a_row] = a4.w;
    *(float4*)&Bs[buf][b_row][b_col] = b4;
    __syncthreads();

    const int NT = H_DIM / 8;   // 512 k-tiles
    for (int t = 0; t < NT; t++) {
        if (t + 1 < NT) {
            a4 = *(const float4*)(Aptr + (size_t)(t + 1) * 8);
            b4 = *(const float4*)(Wptr + (size_t)(t + 1) * 8 * 256);
        }
#pragma unroll
        for (int k = 0; k < 8; k++) {
            float a[8], b[8];
            *(float4*)&a[0] = *(const float4*)&As[buf][k][ty * 8];
            *(float4*)&a[4] = *(const float4*)&As[buf][k][ty * 8 + 4];
            *(float4*)&b[0] = *(const float4*)&Bs[buf][k][tx * 8];
            *(float4*)&b[4] = *(const float4*)&Bs[buf][k][tx * 8 + 4];
#pragma unroll
            for (int i = 0; i < 8; i++)
#pragma unroll
                for (int j = 0; j < 8; j++)
                    acc[i][j] = fmaf(a[i], b[j], acc[i][j]);
        }
        if (t + 1 < NT) {
            buf ^= 1;
            As[buf][a_col + 0][a_row] = a4.x;
            As[buf][a_col + 1][a_row] = a4.y;
            As[buf][a_col + 2][a_row] = a4.z;
            As[buf][a_col + 3][a_row] = a4.w;
            *(float4*)&Bs[buf][b_row][b_col] = b4;
            __syncthreads();
        }
    }

    const int c_col0 = bx * 128 + tx * 8;
#pragma unroll
    for (int i = 0; i < 8; i++) {
        const size_t row = (size_t)(by * 128 + ty * 8 + i);
        float4 v0 = make_float4(acc[i][0], acc[i][1], acc[i][2], acc[i][3]);
        float4 v1 = make_float4(acc[i][4], acc[i][5], acc[i][6], acc[i][7]);
        *(float4*)&g_mid[row * N_TOT + c_col0]     = v0;
        *(float4*)&g_mid[row * N_TOT + c_col0 + 4] = v1;
    }
}

// ---------------------------------------------------------------------------
// Kernel 2: windowed softmax-pool over 64 entries (32 prev-lo + 32 cur-hi),
// per channel d, then interleaved RoPE on the last 64 dims.
// One block per (batch, chunk), one thread per channel (128).
// ---------------------------------------------------------------------------
__global__ void pool_kernel(const float* __restrict__ pbias,
                            float* __restrict__ out)
{
    const int bc = blockIdx.x;       // b * 256 + c
    const int b  = bc >> 8;
    const int c  = bc & 255;
    const int d  = threadIdx.x;      // 0..127

    const float* base = g_mid + (size_t)b * S_DIM * N_TOT;

    float m = -INFINITY, s = 0.f, acc = 0.f;

    // window entries 0..31: previous chunk, lo halves.
    // For c==0 the reference uses gate = NEG (+bias) and kv = 0; those weights
    // underflow to exactly 0 in fp32 once any real (O(1)) entry enters the max,
    // and kv=0 contributes nothing, so skipping them is bit-equivalent.
    if (c > 0) {
        const float* rowp = base + (size_t)(c - 1) * RATIO * N_TOT;
#pragma unroll 4
        for (int j = 0; j < RATIO; j++) {
            float g  = rowp[j * N_TOT + 256 + d] + pbias[j * 128 + d];
            float kv = rowp[j * N_TOT + d];
            float nm = fmaxf(m, g);
            float sc = __expf(m - nm);
            float e  = __expf(g - nm);
            s   = s * sc + e;
            acc = acc * sc + e * kv;
            m = nm;
        }
    }
    {
        // window entries 32..63: current chunk, hi halves
        const float* rowp = base + (size_t)c * RATIO * N_TOT;
#pragma unroll 4
        for (int j = 0; j < RATIO; j++) {
            float g  = rowp[j * N_TOT + 384 + d] + pbias[(RATIO + j) * 128 + d];
            float kv = rowp[j * N_TOT + 128 + d];
            float nm = fmaxf(m, g);
            float sc = __expf(m - nm);
            float e  = __expf(g - nm);
            s   = s * sc + e;
            acc = acc * sc + e * kv;
            m = nm;
        }
    }

    __shared__ float ps[128];
    ps[d] = acc / s;
    __syncthreads();

    float o;
    if (d < 64) {
        o = ps[d];                           // nope part
    } else {
        const int rd = d - 64;               // 0..63 rope dim
        const int p  = rd >> 1;              // pair index 0..31
        // freqs in double: inv_freq = 10000^{-(2p)/64}; ang = (c*32) * inv_freq
        double inv_freq = exp(-(double)(2 * p) / 64.0 * log(10000.0));
        double ang = (double)(c * RATIO) * inv_freq;
        double sn, cs;
        sincos(ang, &sn, &cs);
        float x  = ps[64 + rd];
        float xp = ps[64 + (rd ^ 1)];
        if ((rd & 1) == 0)
            o = x * (float)cs - xp * (float)sn;   // out[2p]   = x0*cos - x1*sin
        else
            o = x * (float)cs + xp * (float)sn;   // out[2p+1] = x1*cos + x0*sin
    }
    out[(size_t)bc * 128 + d] = o;
}

// ---------------------------------------------------------------------------
extern "C" void kernel_launch(void* const* d_in, const int* in_sizes, int n_in,
                              void* d_out, int out_size)
{
    const float* hidden = (const float*)d_in[0];   // (4, 8192, 4096)
    const float* w_kv   = (const float*)d_in[1];   // (4096, 256)
    const float* w_gate = (const float*)d_in[2];   // (4096, 256)
    const float* pbias  = (const float*)d_in[3];   // (64, 128)
    float* out = (float*)d_out;                    // (4, 256, 128)

    dim3 ggrid(4, M_TOT / 128);
    gemm_kernel<<<ggrid, 256>>>(hidden, w_kv, w_gate);
    pool_kernel<<<B_DIM * N_CHUNKS, 128>>>(pbias, out);
}

// round 3
// speedup vs baseline: 2.6123x; 2.6123x over previous
#include <cuda_runtime.h>
#include <cuda_bf16.h>
#include <math.h>
#include <stdint.h>

#define B_DIM   4
#define S_DIM   8192
#define H_DIM   4096
#define RATIO   32
#define M_TOT   (B_DIM * S_DIM)      /* 32768 */
#define N_TOT   512

// ---------------- scratch (device globals: no allocs allowed) ----------------
__device__ __align__(16) float         g_mid[(size_t)M_TOT * N_TOT];   // 64 MB
__device__ __align__(16) __nv_bfloat16 g_Whi[(size_t)N_TOT * H_DIM];   // 4 MB
__device__ __align__(16) __nv_bfloat16 g_Wlo[(size_t)N_TOT * H_DIM];   // 4 MB

// ---------------- helpers ----------------
__device__ __forceinline__ uint32_t smem_u32(const void* p) {
    uint32_t a;
    asm("{ .reg .u64 t; cvta.to.shared.u64 t, %1; cvt.u32.u64 %0, t; }" : "=r"(a) : "l"(p));
    return a;
}

#define CP16(dst, src) \
    asm volatile("cp.async.cg.shared.global [%0], [%1], 16;" \
                 :: "r"(dst), "l"(__cvta_generic_to_global((const void*)(src))) : "memory")
#define CP_COMMIT() asm volatile("cp.async.commit_group;" ::: "memory")
#define CP_WAIT(n)  asm volatile("cp.async.wait_group %0;" :: "n"(n) : "memory")

// m16n8k16 row.col bf16 -> f32 accumulate
#define MMA_BF16(c, a, b0, b1)                                                    \
    asm volatile("mma.sync.aligned.m16n8k16.row.col.f32.bf16.bf16.f32 "           \
        "{%0,%1,%2,%3}, {%4,%5,%6,%7}, {%8,%9}, {%0,%1,%2,%3};"                   \
        : "+f"((c)[0]), "+f"((c)[1]), "+f"((c)[2]), "+f"((c)[3])                  \
        : "r"((a)[0]), "r"((a)[1]), "r"((a)[2]), "r"((a)[3]), "r"(b0), "r"(b1))

// split a float2 into packed bf16x2 hi and lo (lo = x - float(bf16(x)))
__device__ __forceinline__ void cvt_hilo(float2 v, uint32_t& hi, uint32_t& lo) {
    __nv_bfloat162 h2 = __float22bfloat162_rn(v);
    float2 hf = __bfloat1622float2(h2);
    __nv_bfloat162 l2 = __float22bfloat162_rn(make_float2(v.x - hf.x, v.y - hf.y));
    hi = *(uint32_t*)&h2;
    lo = *(uint32_t*)&l2;
}

// ---------------- pre-pass: weights fp32 [K, 256]x2 -> bf16 hi/lo [512, K] ----
__global__ __launch_bounds__(256) void convW_kernel(const float* __restrict__ wkv,
                                                    const float* __restrict__ wg) {
    int k = blockIdx.x * 256 + threadIdx.x;   // 0..4095
    int n = blockIdx.y;                       // 0..511
    const float* w = (n < 256) ? wkv : wg;
    float x = w[(size_t)k * 256 + (n & 255)];
    __nv_bfloat16 h = __float2bfloat16(x);
    g_Whi[(size_t)n * H_DIM + k] = h;
    g_Wlo[(size_t)n * H_DIM + k] = __float2bfloat16(x - __bfloat162float(h));
}

// ---------------- main GEMM ----------------
// g_mid[M, 512] = hidden[M, 4096] @ [w_kv | w_gate]
// BM=128 BN=256 BK=64, 256 threads, 2-stage cp.async, bf16 mma.sync 3-term split.
#define BM 128
#define BN 256
#define BK 64
#define ASTRIDE 72                   /* floats per A smem row (64 + 8 pad)  */
#define BSTRIDE 72                   /* bf16 per B smem row  (64 + 8 pad)  */
#define A_BYTES (BM * ASTRIDE * 4)   /* 36864 */
#define B_BYTES (BN * BSTRIDE * 2)   /* 36864 */
#define OFF_BHI A_BYTES
#define OFF_BLO (A_BYTES + B_BYTES)
#define STAGE_BYTES (A_BYTES + 2 * B_BYTES)   /* 110592 */
#define SMEM_GEMM (2 * STAGE_BYTES)           /* 221184 */

__device__ __forceinline__ void load_stage(uint32_t sb, int s, int kt,
                                           const float* __restrict__ A,
                                           int m0, int n0, int tid) {
    uint32_t st = sb + (uint32_t)s * STAGE_BYTES;
    const float* Ag = A + (size_t)m0 * H_DIM + (size_t)kt * BK;
    const __nv_bfloat16* Wh = g_Whi + (size_t)n0 * H_DIM + (size_t)kt * BK;
    const __nv_bfloat16* Wl = g_Wlo + (size_t)n0 * H_DIM + (size_t)kt * BK;
#pragma unroll
    for (int i = 0; i < 8; i++) {             // A: 128 rows x 256B (16 chunks/row)
        int id = i * 256 + tid;
        int r = id >> 4, cx = id & 15;
        CP16(st + (uint32_t)(r * (ASTRIDE * 4) + cx * 16),
             Ag + (size_t)r * H_DIM + cx * 4);
    }
#pragma unroll
    for (int i = 0; i < 8; i++) {             // Bhi/Blo: 256 rows x 128B (8 chunks/row)
        int id = i * 256 + tid;
        int r = id >> 3, cx = id & 7;
        uint32_t off = (uint32_t)(r * (BSTRIDE * 2) + cx * 16);
        const size_t g = (size_t)r * H_DIM + cx * 8;
        CP16(st + OFF_BHI + off, Wh + g);
        CP16(st + OFF_BLO + off, Wl + g);
    }
}

__global__ __launch_bounds__(256, 1) void gemm_kernel(const float* __restrict__ A) {
    extern __shared__ __align__(16) char smem[];
    uint32_t sb = smem_u32(smem);
    const int tid  = threadIdx.x;
    const int wid  = tid >> 5;
    const int lane = tid & 31;
    const int gID  = lane >> 2;   // 0..7
    const int tig  = lane & 3;    // 0..3
    const int wr   = wid & 1;     // warp m block (0..1) -> 64 rows
    const int wc   = wid >> 1;    // warp n block (0..3) -> 64 cols
    const int n0 = blockIdx.x * BN;
    const int m0 = blockIdx.y * BM;

    float acc[4][8][4];
#pragma unroll
    for (int mt = 0; mt < 4; mt++)
#pragma unroll
        for (int nt = 0; nt < 8; nt++)
#pragma unroll
            for (int j = 0; j < 4; j++) acc[mt][nt][j] = 0.f;

    load_stage(sb, 0, 0, A, m0, n0, tid); CP_COMMIT();
    load_stage(sb, 1, 1, A, m0, n0, tid); CP_COMMIT();

    const int NT = H_DIM / BK;   // 64
    for (int kt = 0; kt < NT; kt++) {
        const int s = kt & 1;
        if (kt < NT - 1) { CP_WAIT(1); } else { CP_WAIT(0); }
        __syncthreads();

        const float* As = (const float*)(smem + (size_t)s * STAGE_BYTES);
        const __nv_bfloat16* Bh =
            (const __nv_bfloat16*)(smem + (size_t)s * STAGE_BYTES + OFF_BHI);
        const __nv_bfloat16* Bl =
            (const __nv_bfloat16*)(smem + (size_t)s * STAGE_BYTES + OFF_BLO);

#pragma unroll
        for (int k16 = 0; k16 < 4; k16++) {
            const int kb = k16 * 16;
            // --- A fragments: load fp32 from smem, split to bf16 hi/lo ---
            uint32_t ahi[4][4], alo[4][4];
#pragma unroll
            for (int mt = 0; mt < 4; mt++) {
                const int r0 = wr * 64 + mt * 16 + gID;
                const int kc = kb + 2 * tig;
                float2 v;
                v = *(const float2*)&As[r0 * ASTRIDE + kc];
                cvt_hilo(v, ahi[mt][0], alo[mt][0]);
                v = *(const float2*)&As[(r0 + 8) * ASTRIDE + kc];
                cvt_hilo(v, ahi[mt][1], alo[mt][1]);
                v = *(const float2*)&As[r0 * ASTRIDE + kc + 8];
                cvt_hilo(v, ahi[mt][2], alo[mt][2]);
                v = *(const float2*)&As[(r0 + 8) * ASTRIDE + kc + 8];
                cvt_hilo(v, ahi[mt][3], alo[mt][3]);
            }
            // --- B fragments + MMAs ---
#pragma unroll
            for (int nt = 0; nt < 8; nt++) {
                const int n = wc * 64 + nt * 8 + gID;
                const int kc = kb + 2 * tig;
                uint32_t bh0 = *(const uint32_t*)&Bh[n * BSTRIDE + kc];
                uint32_t bh1 = *(const uint32_t*)&Bh[n * BSTRIDE + kc + 8];
                uint32_t bl0 = *(const uint32_t*)&Bl[n * BSTRIDE + kc];
                uint32_t bl1 = *(const uint32_t*)&Bl[n * BSTRIDE + kc + 8];
#pragma unroll
                for (int mt = 0; mt < 4; mt++) {
                    MMA_BF16(acc[mt][nt], ahi[mt], bh0, bh1);
                    MMA_BF16(acc[mt][nt], ahi[mt], bl0, bl1);
                    MMA_BF16(acc[mt][nt], alo[mt], bh0, bh1);
                }
            }
        }
        __syncthreads();
        if (kt + 2 < NT) {
            load_stage(sb, s, kt + 2, A, m0, n0, tid);
            CP_COMMIT();
        }
    }

    // epilogue: write fp32 accumulators to g_mid
#pragma unroll
    for (int mt = 0; mt < 4; mt++) {
        const int r0 = m0 + wr * 64 + mt * 16 + gID;
#pragma unroll
        for (int nt = 0; nt < 8; nt++) {
            const int c0 = n0 + wc * 64 + nt * 8 + 2 * tig;
            *(float2*)&g_mid[(size_t)r0 * N_TOT + c0] =
                make_float2(acc[mt][nt][0], acc[mt][nt][1]);
            *(float2*)&g_mid[(size_t)(r0 + 8) * N_TOT + c0] =
                make_float2(acc[mt][nt][2], acc[mt][nt][3]);
        }
    }
}

// ---------------- kernel 2: windowed softmax-pool + RoPE ----------------
__global__ void pool_kernel(const float* __restrict__ pbias,
                            float* __restrict__ out)
{
    const int bc = blockIdx.x;       // b * 256 + c
    const int b  = bc >> 8;
    const int c  = bc & 255;
    const int d  = threadIdx.x;      // 0..127

    const float* base = g_mid + (size_t)b * S_DIM * N_TOT;

    float m = -INFINITY, s = 0.f, acc = 0.f;

    if (c > 0) {
        const float* rowp = base + (size_t)(c - 1) * RATIO * N_TOT;
#pragma unroll 4
        for (int j = 0; j < RATIO; j++) {
            float g  = rowp[j * N_TOT + 256 + d] + pbias[j * 128 + d];
            float kv = rowp[j * N_TOT + d];
            float nm = fmaxf(m, g);
            float sc = __expf(m - nm);
            float e  = __expf(g - nm);
            s   = s * sc + e;
            acc = acc * sc + e * kv;
            m = nm;
        }
    }
    {
        const float* rowp = base + (size_t)c * RATIO * N_TOT;
#pragma unroll 4
        for (int j = 0; j < RATIO; j++) {
            float g  = rowp[j * N_TOT + 384 + d] + pbias[(RATIO + j) * 128 + d];
            float kv = rowp[j * N_TOT + 128 + d];
            float nm = fmaxf(m, g);
            float sc = __expf(m - nm);
            float e  = __expf(g - nm);
            s   = s * sc + e;
            acc = acc * sc + e * kv;
            m = nm;
        }
    }

    __shared__ float ps[128];
    ps[d] = acc / s;
    __syncthreads();

    float o;
    if (d < 64) {
        o = ps[d];
    } else {
        const int rd = d - 64;
        const int p  = rd >> 1;
        double inv_freq = exp(-(double)(2 * p) / 64.0 * log(10000.0));
        double ang = (double)(c * RATIO) * inv_freq;
        double sn, cs;
        sincos(ang, &sn, &cs);
        float x  = ps[64 + rd];
        float xp = ps[64 + (rd ^ 1)];
        if ((rd & 1) == 0)
            o = x * (float)cs - xp * (float)sn;
        else
            o = x * (float)cs + xp * (float)sn;
    }
    out[(size_t)bc * 128 + d] = o;
}

// ---------------------------------------------------------------------------
extern "C" void kernel_launch(void* const* d_in, const int* in_sizes, int n_in,
                              void* d_out, int out_size)
{
    const float* hidden = (const float*)d_in[0];   // (4, 8192, 4096)
    const float* w_kv   = (const float*)d_in[1];   // (4096, 256)
    const float* w_gate = (const float*)d_in[2];   // (4096, 256)
    const float* pbias  = (const float*)d_in[3];   // (64, 128)
    float* out = (float*)d_out;                    // (4, 256, 128)

    cudaFuncSetAttribute(gemm_kernel,
                         cudaFuncAttributeMaxDynamicSharedMemorySize, SMEM_GEMM);

    convW_kernel<<<dim3(H_DIM / 256, N_TOT), 256>>>(w_kv, w_gate);

    dim3 ggrid(N_TOT / BN, M_TOT / BM);   // (2, 256)
    gemm_kernel<<<ggrid, 256, SMEM_GEMM>>>(hidden);

    pool_kernel<<<B_DIM * (S_DIM / RATIO), 128>>>(pbias, out);
}

// round 5
// speedup vs baseline: 2.9429x; 1.1266x over previous
#include <cuda_runtime.h>
#include <cuda_bf16.h>
#include <math.h>
#include <stdint.h>

#define B_DIM   4
#define S_DIM   8192
#define H_DIM   4096
#define RATIO   32
#define M_TOT   (B_DIM * S_DIM)      /* 32768 */
#define N_TOT   512

// ---------------- scratch (device globals: no allocs allowed) ----------------
__device__ __align__(16) float         g_mid[(size_t)M_TOT * N_TOT];   // 64 MB
__device__ __align__(16) __nv_bfloat16 g_Whi[(size_t)N_TOT * H_DIM];   // 4 MB
__device__ __align__(16) __nv_bfloat16 g_Wlo[(size_t)N_TOT * H_DIM];   // 4 MB

// ---------------- helpers ----------------
__device__ __forceinline__ uint32_t smem_u32(const void* p) {
    uint32_t a;
    asm("{ .reg .u64 t; cvta.to.shared.u64 t, %1; cvt.u32.u64 %0, t; }" : "=r"(a) : "l"(p));
    return a;
}

#define CP16(dst, src) \
    asm volatile("cp.async.cg.shared.global [%0], [%1], 16;" \
                 :: "r"(dst), "l"(__cvta_generic_to_global((const void*)(src))) : "memory")
#define CP_COMMIT() asm volatile("cp.async.commit_group;" ::: "memory")
#define CP_WAIT(n)  asm volatile("cp.async.wait_group %0;" :: "n"(n) : "memory")

#define LDSM_X4(r, addr)                                                          \
    asm volatile("ldmatrix.sync.aligned.m8n8.x4.shared.b16 {%0,%1,%2,%3}, [%4];"  \
        : "=r"((r)[0]), "=r"((r)[1]), "=r"((r)[2]), "=r"((r)[3]) : "r"(addr))

#define STS128(addr, r0, r1, r2, r3)                                              \
    asm volatile("st.shared.v4.b32 [%0], {%1,%2,%3,%4};"                          \
        :: "r"(addr), "r"(r0), "r"(r1), "r"(r2), "r"(r3) : "memory")

// m16n8k16 row.col bf16 -> f32 accumulate
#define MMA_BF16(c, a, b0, b1)                                                    \
    asm volatile("mma.sync.aligned.m16n8k16.row.col.f32.bf16.bf16.f32 "           \
        "{%0,%1,%2,%3}, {%4,%5,%6,%7}, {%8,%9}, {%0,%1,%2,%3};"                   \
        : "+f"((c)[0]), "+f"((c)[1]), "+f"((c)[2]), "+f"((c)[3])                  \
        : "r"((a)[0]), "r"((a)[1]), "r"((a)[2]), "r"((a)[3]), "r"(b0), "r"(b1))

__device__ __forceinline__ void cvt_hilo2(float x, float y, uint32_t& hi, uint32_t& lo) {
    __nv_bfloat162 h2 = __float22bfloat162_rn(make_float2(x, y));
    float2 hf = __bfloat1622float2(h2);
    __nv_bfloat162 l2 = __float22bfloat162_rn(make_float2(x - hf.x, y - hf.y));
    hi = *(uint32_t*)&h2;
    lo = *(uint32_t*)&l2;
}

// ---------------- pre-pass: weights fp32 [K, 256]x2 -> bf16 hi/lo [512, K] ----
__global__ __launch_bounds__(256) void convW_kernel(const float* __restrict__ wkv,
                                                    const float* __restrict__ wg) {
    int k = blockIdx.x * 256 + threadIdx.x;   // 0..4095
    int n = blockIdx.y;                       // 0..511
    const float* w = (n < 256) ? wkv : wg;
    float x = w[(size_t)k * 256 + (n & 255)];
    __nv_bfloat16 h = __float2bfloat16(x);
    g_Whi[(size_t)n * H_DIM + k] = h;
    g_Wlo[(size_t)n * H_DIM + k] = __float2bfloat16(x - __bfloat162float(h));
}

// ---------------- main GEMM ----------------
// g_mid[M, 512] = hidden[M, 4096] @ [w_kv | w_gate]
// BM=128 BN=256 BK=64, 512 threads.
// B: cp.async bf16 hi/lo, 2 stages, XOR-swizzled, ldmatrix.
// A: LDG fp32 (prefetched one ktile ahead) -> reg -> hi/lo split -> swizzled
//    smem (double buffered) -> ldmatrix.
#define BM 128
#define BN 256
#define BK 64
// smem map: [0, 131072) B stages (stage s at s*65536: hi 32KB, lo 32KB)
//           [131072, 196608) A bf16 buffers (buf b at +b*32768: hi 16KB, lo 16KB)
#define OFF_ABF 131072
#define B_STAGE 65536
#define SMEM_GEMM (OFF_ABF + 2 * 32768)

__device__ __forceinline__ void load_B(uint32_t sb, int s, int kt, int n0, int tid) {
    uint32_t bs = sb + (uint32_t)s * B_STAGE;
    const __nv_bfloat16* Wh = g_Whi + (size_t)n0 * H_DIM + (size_t)kt * BK;
    const __nv_bfloat16* Wl = g_Wlo + (size_t)n0 * H_DIM + (size_t)kt * BK;
#pragma unroll
    for (int i = 0; i < 4; i++) {
        int id = i * 512 + tid;            // 0..2047
        int r = id >> 3, c = id & 7;       // row 0..255, 16B chunk 0..7
        uint32_t off = (uint32_t)(r * 128 + ((c ^ (r & 7)) << 4));
        const size_t g = (size_t)r * H_DIM + c * 8;
        CP16(bs + off, Wh + g);
        CP16(bs + 32768 + off, Wl + g);
    }
}

__global__ __launch_bounds__(512, 1) void gemm_kernel(const float* __restrict__ A) {
    extern __shared__ __align__(1024) char smem[];
    uint32_t sb = smem_u32(smem);
    const int tid  = threadIdx.x;
    const int wid  = tid >> 5;
    const int lane = tid & 31;
    const int gID  = lane >> 2;   // 0..7
    const int tig  = lane & 3;    // 0..3
    const int wr   = wid & 3;     // m block (32 rows each)
    const int wc   = wid >> 2;    // n block (64 cols each)
    const int n0 = blockIdx.x * BN;
    const int m0 = blockIdx.y * BM;

    // ldmatrix per-lane constants (matrix index m = lane>>3)
    const int mQ  = lane >> 3;
    const int l7  = lane & 7;
    const uint32_t swz  = (uint32_t)l7;
    const uint32_t rowA = (uint32_t)((wr * 32 + (mQ & 1) * 8 + l7) * 128);
    const int khA = mQ >> 1;
    const uint32_t rowB = (uint32_t)((wc * 64 + (mQ >> 1) * 8 + l7) * 128);
    const int khB = mQ & 1;

    // A convert/load identity: row cr, quarter cq (16 floats)
    const int cr = tid >> 2;      // 0..127
    const int cq = tid & 3;       // 0..3
    const float* Abase = A + (size_t)(m0 + cr) * H_DIM + cq * 16;

    float acc[2][8][4];
#pragma unroll
    for (int mt = 0; mt < 2; mt++)
#pragma unroll
        for (int nt = 0; nt < 8; nt++)
#pragma unroll
            for (int j = 0; j < 4; j++) acc[mt][nt][j] = 0.f;

    float4 R[4];

    // ---- prologue ----
    // R <- A(kt=0); convert -> Abf[0]; R <- A(kt=1)
#pragma unroll
    for (int j = 0; j < 4; j++) R[j] = *(const float4*)(Abase + j * 4);
    {
        uint32_t hb = sb + OFF_ABF + (uint32_t)(cr * 128);
#pragma unroll
        for (int j = 0; j < 2; j++) {
            int chunk = cq * 2 + j;
            uint32_t r0, r1, r2, r3, s0, s1, s2, s3;
            cvt_hilo2(R[2*j].x,   R[2*j].y,   r0, s0);
            cvt_hilo2(R[2*j].z,   R[2*j].w,   r1, s1);
            cvt_hilo2(R[2*j+1].x, R[2*j+1].y, r2, s2);
            cvt_hilo2(R[2*j+1].z, R[2*j+1].w, r3, s3);
            uint32_t off = (uint32_t)((chunk ^ (cr & 7)) << 4);
            STS128(hb + off, r0, r1, r2, r3);
            STS128(hb + 16384 + off, s0, s1, s2, s3);
        }
    }
#pragma unroll
    for (int j = 0; j < 4; j++) R[j] = *(const float4*)(Abase + BK + j * 4);

    load_B(sb, 0, 0, n0, tid); CP_COMMIT();
    load_B(sb, 1, 1, n0, tid); CP_COMMIT();

    const int NT = H_DIM / BK;   // 64
    for (int kt = 0; kt < NT; kt++) {
        const int s = kt & 1;

        // convert A(kt+1) (held in R) into Abf[(kt+1)&1]
        if (kt + 1 < NT) {
            uint32_t hb = sb + OFF_ABF + (uint32_t)(((kt + 1) & 1) * 32768 + cr * 128);
#pragma unroll
            for (int j = 0; j < 2; j++) {
                int chunk = cq * 2 + j;
                uint32_t r0, r1, r2, r3, s0, s1, s2, s3;
                cvt_hilo2(R[2*j].x,   R[2*j].y,   r0, s0);
                cvt_hilo2(R[2*j].z,   R[2*j].w,   r1, s1);
                cvt_hilo2(R[2*j+1].x, R[2*j+1].y, r2, s2);
                cvt_hilo2(R[2*j+1].z, R[2*j+1].w, r3, s3);
                uint32_t off = (uint32_t)((chunk ^ (cr & 7)) << 4);
                STS128(hb + off, r0, r1, r2, r3);
                STS128(hb + 16384 + off, s0, s1, s2, s3);
            }
        }

        if (kt < NT - 1) { CP_WAIT(1); } else { CP_WAIT(0); }
        __syncthreads();   // B(kt) + Abf[kt&1] visible to all warps

        // prefetch A(kt+2) into R (consumed next iteration's convert)
        if (kt + 2 < NT) {
#pragma unroll
            for (int j = 0; j < 4; j++)
                R[j] = *(const float4*)(Abase + (size_t)(kt + 2) * BK + j * 4);
        }

        // ---- MMA phase ----
        const uint32_t Bh = sb + (uint32_t)s * B_STAGE;
        const uint32_t Bl = Bh + 32768;
        const uint32_t Ah = sb + OFF_ABF + (uint32_t)s * 32768;
        const uint32_t Al = Ah + 16384;

#pragma unroll
        for (int q = 0; q < 4; q++) {
            uint32_t ah[2][4], al[2][4];
            const uint32_t aoff = rowA + (uint32_t)((((2 * q + khA) ^ swz) << 4));
#pragma unroll
            for (int mt = 0; mt < 2; mt++) {
                LDSM_X4(ah[mt], Ah + aoff + mt * 2048);
                LDSM_X4(al[mt], Al + aoff + mt * 2048);
            }
            const uint32_t boff = rowB + (uint32_t)(((2 * q + khB) ^ swz) << 4);
#pragma unroll
            for (int p = 0; p < 4; p++) {
                uint32_t bh[4], bl[4];
                LDSM_X4(bh, Bh + boff + p * 2048);
                LDSM_X4(bl, Bl + boff + p * 2048);
#pragma unroll
                for (int mt = 0; mt < 2; mt++) {
                    MMA_BF16(acc[mt][2*p],   ah[mt], bh[0], bh[1]);
                    MMA_BF16(acc[mt][2*p],   ah[mt], bl[0], bl[1]);
                    MMA_BF16(acc[mt][2*p],   al[mt], bh[0], bh[1]);
                    MMA_BF16(acc[mt][2*p+1], ah[mt], bh[2], bh[3]);
                    MMA_BF16(acc[mt][2*p+1], ah[mt], bl[2], bl[3]);
                    MMA_BF16(acc[mt][2*p+1], al[mt], bh[2], bh[3]);
                }
            }
        }

        __syncthreads();   // everyone done reading B stage s / before refill
        if (kt + 2 < NT) {
            load_B(sb, s, kt + 2, n0, tid);
            CP_COMMIT();
        }
    }

    // ---- epilogue ----
#pragma unroll
    for (int mt = 0; mt < 2; mt++) {
        const int r0 = m0 + wr * 32 + mt * 16 + gID;
#pragma unroll
        for (int nt = 0; nt < 8; nt++) {
            const int c0 = n0 + wc * 64 + nt * 8 + 2 * tig;
            *(float2*)&g_mid[(size_t)r0 * N_TOT + c0] =
                make_float2(acc[mt][nt][0], acc[mt][nt][1]);
            *(float2*)&g_mid[(size_t)(r0 + 8) * N_TOT + c0] =
                make_float2(acc[mt][nt][2], acc[mt][nt][3]);
        }
    }
}

// ---------------- kernel 2: windowed softmax-pool + RoPE ----------------
__global__ void pool_kernel(const float* __restrict__ pbias,
                            float* __restrict__ out)
{
    const int bc = blockIdx.x;       // b * 256 + c
    const int b  = bc >> 8;
    const int c  = bc & 255;
    const int d  = threadIdx.x;      // 0..127

    const float* base = g_mid + (size_t)b * S_DIM * N_TOT;

    float m = -INFINITY, s = 0.f, acc = 0.f;

    if (c > 0) {
        const float* rowp = base + (size_t)(c - 1) * RATIO * N_TOT;
#pragma unroll 4
        for (int j = 0; j < RATIO; j++) {
            float g  = rowp[j * N_TOT + 256 + d] + pbias[j * 128 + d];
            float kv = rowp[j * N_TOT + d];
            float nm = fmaxf(m, g);
            float sc = __expf(m - nm);
            float e  = __expf(g - nm);
            s   = s * sc + e;
            acc = acc * sc + e * kv;
            m = nm;
        }
    }
    {
        const float* rowp = base + (size_t)c * RATIO * N_TOT;
#pragma unroll 4
        for (int j = 0; j < RATIO; j++) {
            float g  = rowp[j * N_TOT + 384 + d] + pbias[(RATIO + j) * 128 + d];
            float kv = rowp[j * N_TOT + 128 + d];
            float nm = fmaxf(m, g);
            float sc = __expf(m - nm);
            float e  = __expf(g - nm);
            s   = s * sc + e;
            acc = acc * sc + e * kv;
            m = nm;
        }
    }

    __shared__ float ps[128];
    ps[d] = acc / s;
    __syncthreads();

    float o;
    if (d < 64) {
        o = ps[d];
    } else {
        const int rd = d - 64;
        const int p  = rd >> 1;
        double inv_freq = exp(-(double)(2 * p) / 64.0 * log(10000.0));
        double ang = (double)(c * RATIO) * inv_freq;
        double sn, cs;
        sincos(ang, &sn, &cs);
        float x  = ps[64 + rd];
        float xp = ps[64 + (rd ^ 1)];
        if ((rd & 1) == 0)
            o = x * (float)cs - xp * (float)sn;
        else
            o = x * (float)cs + xp * (float)sn;
    }
    out[(size_t)bc * 128 + d] = o;
}

// ---------------------------------------------------------------------------
extern "C" void kernel_launch(void* const* d_in, const int* in_sizes, int n_in,
                              void* d_out, int out_size)
{
    const float* hidden = (const float*)d_in[0];   // (4, 8192, 4096)
    const float* w_kv   = (const float*)d_in[1];   // (4096, 256)
    const float* w_gate = (const float*)d_in[2];   // (4096, 256)
    const float* pbias  = (const float*)d_in[3];   // (64, 128)
    float* out = (float*)d_out;                    // (4, 256, 128)

    cudaFuncSetAttribute(gemm_kernel,
                         cudaFuncAttributeMaxDynamicSharedMemorySize, SMEM_GEMM);

    convW_kernel<<<dim3(H_DIM / 256, N_TOT), 256>>>(w_kv, w_gate);

    dim3 ggrid(N_TOT / BN, M_TOT / BM);   // (2, 256)
    gemm_kernel<<<ggrid, 512, SMEM_GEMM>>>(hidden);

    pool_kernel<<<B_DIM * (S_DIM / RATIO), 128>>>(pbias, out);
}